// round 12
// baseline (speedup 1.0000x reference)
#include <cuda_runtime.h>

// out = chem @ (Wout @ Wv)^T + (Wout @ bv + bout)   (softmax over singleton == 1)
//
// Octet scheme with float4 I/O and 32-reg M (3 CTAs/SM):
//   lane o=t&7 loads float4 quarter g=o&3 of row h=o>>2 (coalesced LDG.128).
//   Gather both rows' quarter via variable-index shfl. Lane computes partials
//   for output pairs sigma(m) = 4h + 2(g1^(m>>1)) + (m&1) of BOTH rows
//   (M = 4 dims x 4 pairs = 16 f32x2 regs, shared across rows).
//   xor2 round aligns pairs; xor1 round cross-feeds rows (lane keeps row
//   h^g0) -> each lane ends with 4 consecutive floats of one row:
//   ONE coalesced STG.128 at slot (p + dlt). Bias seeded once via P_A.
// Persistent grid, 4-buffer register pipeline (3 tiles ahead), 24 warps/SM.

#define DIMN 16
#define TB4  256          // float4s per tile (TPT=1)
#define NCTA 444          // 3 per SM, persistent

typedef unsigned long long ull;

__device__ __forceinline__ ull dup2f(float v) {
    ull r; asm("mov.b64 %0, {%1, %1};" : "=l"(r) : "f"(v)); return r;
}
__device__ __forceinline__ void unpack2f(ull v, float& lo, float& hi) {
    asm("mov.b64 {%0, %1}, %2;" : "=f"(lo), "=f"(hi) : "l"(v));
}
__device__ __forceinline__ void ffma2(ull& d, ull a, ull b) {
    asm("fma.rn.f32x2 %0, %1, %2, %3;" : "=l"(d) : "l"(a), "l"(b), "l"(d));
}
__device__ __forceinline__ ull mul2(ull a, ull b) {
    ull r; asm("mul.rn.f32x2 %0, %1, %2;" : "=l"(r) : "l"(a), "l"(b)); return r;
}
__device__ __forceinline__ ull add2(ull a, ull b) {
    ull r; asm("add.rn.f32x2 %0, %1, %2;" : "=l"(r) : "l"(a), "l"(b)); return r;
}
__device__ __forceinline__ ull shx(ull v, int m) {
    return __shfl_xor_sync(0xffffffffu, v, m);
}

template <bool GUARD>
__device__ __forceinline__ float4 load_one(const float4* __restrict__ gin,
                                           int p, bool live, int total4) {
    float4 r = make_float4(0.f, 0.f, 0.f, 0.f);
    if (live && (!GUARD || p < total4)) r = __ldcs(&gin[p]);
    return r;
}

template <bool GUARD>
__device__ __forceinline__ void task(float4 v, int p,
                                     float4* __restrict__ gout,
                                     const ull M[4][4],
                                     ull cbE, ull cbO,
                                     int idxA, int idxB, int dlt,
                                     int total4) {
    // Gather my-row (a) and other-row (b) quarter-g inputs.
    float ax = __shfl_sync(0xffffffffu, v.x, idxA);
    float ay = __shfl_sync(0xffffffffu, v.y, idxA);
    float az = __shfl_sync(0xffffffffu, v.z, idxA);
    float aw = __shfl_sync(0xffffffffu, v.w, idxA);
    float bx = __shfl_sync(0xffffffffu, v.x, idxB);
    float by = __shfl_sync(0xffffffffu, v.y, idxB);
    float bz = __shfl_sync(0xffffffffu, v.z, idxB);
    float bw = __shfl_sync(0xffffffffu, v.w, idxB);

    ull a0 = dup2f(ax), a1 = dup2f(ay), a2 = dup2f(az), a3 = dup2f(aw);
    ull b0 = dup2f(bx), b1 = dup2f(by), b2 = dup2f(bz), b3 = dup2f(bw);

    // Partials: P_A (row h^g0, bias-seeded) and P_B (other row, unseeded).
    ull PA0 = cbE, PA1 = cbO;
    ffma2(PA0, M[0][0], a0);          ffma2(PA1, M[0][1], a0);
    ull PA2 = mul2(M[0][2], a0);      ull PA3 = mul2(M[0][3], a0);
    ull PB0 = mul2(M[0][0], b0);      ull PB1 = mul2(M[0][1], b0);
    ull PB2 = mul2(M[0][2], b0);      ull PB3 = mul2(M[0][3], b0);
#pragma unroll
    for (int il = 1; il < 4; il++) {
        ull ai = (il == 1) ? a1 : (il == 2) ? a2 : a3;
        ull bi = (il == 1) ? b1 : (il == 2) ? b2 : b3;
        ffma2(PA0, M[il][0], ai); ffma2(PA1, M[il][1], ai);
        ffma2(PA2, M[il][2], ai); ffma2(PA3, M[il][3], ai);
        ffma2(PB0, M[il][0], bi); ffma2(PB1, M[il][1], bi);
        ffma2(PB2, M[il][2], bi); ffma2(PB3, M[il][3], bi);
    }

    // xor2: align pairs within the g1 dimension.
    ull U0A = add2(PA0, shx(PA2, 2));
    ull U1A = add2(PA1, shx(PA3, 2));
    ull U0B = add2(PB0, shx(PB2, 2));
    ull U1B = add2(PB1, shx(PB3, 2));
    // xor1: cross-feed rows; lane keeps its own row (h^g0) result.
    ull F0 = add2(U0A, shx(U0B, 1));
    ull F1 = add2(U1A, shx(U1B, 1));

    int s = p + dlt;
    if (!GUARD || s < total4) {
        float o0, o1, o2, o3;
        unpack2f(F0, o0, o1);
        unpack2f(F1, o2, o3);
        __stcs(&gout[s], make_float4(o0, o1, o2, o3));
    }
}

template <bool GUARD>
__global__ __launch_bounds__(256, 3)
void xattn_kernel(const float4* __restrict__ gin,
                  float4* __restrict__ gout,
                  const float* __restrict__ w_in,
                  const float* __restrict__ b_in,
                  const float* __restrict__ w_out,
                  const float* __restrict__ b_out,
                  int total4, int ntiles) {
    __shared__ __align__(16) float2 sB[128];  // [i*8+pr] = (M[2pr][i], M[2pr+1][i])
    __shared__ float2 sC[8];                  // [pr] = (c[2pr], c[2pr+1])

    int t = threadIdx.x;

    // ---- per-CTA weight folding (no separate setup launch) ----
    if (t < 128) {
        int i = t >> 3, pr = t & 7;
        float m0 = 0.f, m1 = 0.f;
#pragma unroll
        for (int k = 0; k < DIMN; k++) {
            float wv = w_in[(2 * DIMN + k) * DIMN + i];   // Wv rows 32..47, col i
            m0 += w_out[(2 * pr) * DIMN + k] * wv;
            m1 += w_out[(2 * pr + 1) * DIMN + k] * wv;
        }
        sB[t] = make_float2(m0, m1);
        if (i == 0) {
            float c0 = b_out[2 * pr], c1 = b_out[2 * pr + 1];
#pragma unroll
            for (int k = 0; k < DIMN; k++) {
                float bv = b_in[2 * DIMN + k];
                c0 += w_out[(2 * pr) * DIMN + k] * bv;
                c1 += w_out[(2 * pr + 1) * DIMN + k] * bv;
            }
            sC[pr] = make_float2(c0, c1);
        }
    }
    __syncthreads();

    const int lane = t & 31;
    const int o  = t & 7;
    const int g  = o & 3;
    const int h  = o >> 2;
    const int g0 = o & 1;
    const int g1 = (o >> 1) & 1;

    // M for dims 4g..4g+3 x pairs sigma(m) = 4h + 2(g1^(m>>1)) + (m&1).
    ull Mreg[4][4];
#pragma unroll
    for (int il = 0; il < 4; il++) {
#pragma unroll
        for (int m = 0; m < 4; m++) {
            int pr = 4 * h + 2 * (g1 ^ (m >> 1)) + (m & 1);
            Mreg[il][m] = *(const ull*)&sB[(4 * g + il) * 8 + pr];
        }
    }
    ull cbE = *(const ull*)&sC[4 * h + 2 * g1];
    ull cbO = *(const ull*)&sC[4 * h + 2 * g1 + 1];

    // Gather lane indices: a = my-row quarter (row h^g0), b = other row.
    const int idxA = lane ^ (g0 ? 4 : 0);
    const int idxB = idxA ^ 4;
    // Store slot delta: slot = 4*(h^g0) + 2h + g1 within the octet.
    const int dlt = (4 * (h ^ g0) + 2 * h + g1) - o;

    const int S    = gridDim.x;
    const int step = S * TB4;
    int T = blockIdx.x;
    if (T >= ntiles) return;
    int p = T * TB4 + t;

    float4 v0, v1, v2, v3;
    v0 = load_one<GUARD>(gin, p,            true,              total4);
    v1 = load_one<GUARD>(gin, p + step,     T + S     < ntiles, total4);
    v2 = load_one<GUARD>(gin, p + 2 * step, T + 2 * S < ntiles, total4);

    while (true) {
        v3 = load_one<GUARD>(gin, p + 3 * step, T + 3 * S < ntiles, total4);
        task<GUARD>(v0, p, gout, Mreg, cbE, cbO, idxA, idxB, dlt, total4);
        T += S; if (T >= ntiles) return; p += step;

        v0 = load_one<GUARD>(gin, p + 3 * step, T + 3 * S < ntiles, total4);
        task<GUARD>(v1, p, gout, Mreg, cbE, cbO, idxA, idxB, dlt, total4);
        T += S; if (T >= ntiles) return; p += step;

        v1 = load_one<GUARD>(gin, p + 3 * step, T + 3 * S < ntiles, total4);
        task<GUARD>(v2, p, gout, Mreg, cbE, cbO, idxA, idxB, dlt, total4);
        T += S; if (T >= ntiles) return; p += step;

        v2 = load_one<GUARD>(gin, p + 3 * step, T + 3 * S < ntiles, total4);
        task<GUARD>(v3, p, gout, Mreg, cbE, cbO, idxA, idxB, dlt, total4);
        T += S; if (T >= ntiles) return; p += step;
    }
}

extern "C" void kernel_launch(void* const* d_in, const int* in_sizes, int n_in,
                              void* d_out, int out_size) {
    // inputs: 0 fp_16 (unused), 1 chem_16, 2 in_proj_weight, 3 in_proj_bias,
    //         4 out_proj_weight, 5 out_proj_bias
    const float* chem  = (const float*)d_in[1];
    const float* w_in  = (const float*)d_in[2];
    const float* b_in  = (const float*)d_in[3];
    const float* w_out = (const float*)d_in[4];
    const float* b_out = (const float*)d_in[5];

    int total4 = in_sizes[1] / 4;            // float4 count
    int ntiles = (total4 + TB4 - 1) / TB4;
    int blocks = ntiles < NCTA ? ntiles : NCTA;

    if (total4 % TB4 == 0 && total4 % 8 == 0) {
        xattn_kernel<false><<<blocks, 256>>>((const float4*)chem,
                                             (float4*)d_out,
                                             w_in, b_in, w_out, b_out,
                                             total4, ntiles);
    } else {
        xattn_kernel<true><<<blocks, 256>>>((const float4*)chem,
                                            (float4*)d_out,
                                            w_in, b_in, w_out, b_out,
                                            total4, ntiles);
    }
}

// round 13
// speedup vs baseline: 1.3541x; 1.3541x over previous
#include <cuda_runtime.h>
#include <cstdint>

// out = chem @ (Wout @ Wv)^T + (Wout @ bv + bout)   (softmax over singleton == 1)
//
// Tensor-core path: the folded 16x16 matvec is a GEMM (N=K=16) done with
// mma.sync.m16n8k8.tf32, 3-term compensated (x_hi*M_hi + x_hi*M_lo + x_lo*M_hi,
// hi = fp32 masked to tf32 bits, lo = exact residual) -> fp32-grade accuracy.
// A-fragments are loaded DIRECTLY from gmem with 8 LDG.32 per warp-tile
// (each request spans a full 512B region: zero wasted sectors, no smem, no
// shfl); D-fragments store directly with 4 STG.64 (full 32B sectors).
// ~56 warp-inst per KB (vs ~110 for the FFMA2 path). Persistent grid,
// per-warp independent streaming, 3-buffer LDG pipeline.

#define DIMN 16
#define NCTA 296

typedef unsigned int u32;

__device__ __forceinline__ void mma_tf32(float& d0, float& d1, float& d2, float& d3,
                                         u32 a0, u32 a1, u32 a2, u32 a3,
                                         u32 b0, u32 b1) {
    asm("mma.sync.aligned.m16n8k8.row.col.f32.tf32.tf32.f32 "
        "{%0,%1,%2,%3}, {%4,%5,%6,%7}, {%8,%9}, {%0,%1,%2,%3};"
        : "+f"(d0), "+f"(d1), "+f"(d2), "+f"(d3)
        : "r"(a0), "r"(a1), "r"(a2), "r"(a3), "r"(b0), "r"(b1));
}

// Tile = 16 consecutive rows = 256 floats = 1 KB, processed by one warp.
// Lane (grp = lane>>2, tid = lane&3) loads x[grp + 8rr][tid + 4cc], rr<2, cc<4.
template <bool GUARD>
__device__ __forceinline__ void load_tile(float v[8], const float* __restrict__ gin,
                                          int lbase, bool live, int total) {
    if (!live) return;
#pragma unroll
    for (int j = 0; j < 8; j++) {
        int e = lbase + (j >> 2) * 128 + (j & 3) * 4;
        if (GUARD) v[j] = (e < total) ? gin[e] : 0.f;
        else       v[j] = gin[e];
    }
}

template <bool GUARD>
__device__ __forceinline__ void proc_tile(const float v[8], float* __restrict__ gout,
                                          int T, int grp, int tid, int total,
                                          const u32 bHi[2][2][2],
                                          const u32 bLo[2][2][2],
                                          const float cb[2][2]) {
    // Split x into tf32-exact hi + residual lo.
    u32 ah[8], al[8];
#pragma unroll
    for (int j = 0; j < 8; j++) {
        u32 u = __float_as_uint(v[j]) & 0xffffe000u;
        ah[j] = u;
        al[j] = __float_as_uint(v[j] - __uint_as_float(u));
    }
    int sbase = T * 256 + grp * 16 + 2 * tid;
#pragma unroll
    for (int nh = 0; nh < 2; nh++) {
        float d0 = cb[nh][0], d1 = cb[nh][1], d2 = d0, d3 = d1;  // bias seed
#pragma unroll
        for (int kk = 0; kk < 2; kk++) {
            // A-frag: a0=(grp,tid+8kk) a1=(grp+8,·) a2=(grp,tid+4+8kk) a3=(grp+8,·)
            u32 A0 = ah[2 * kk], A1 = ah[4 + 2 * kk];
            u32 A2 = ah[2 * kk + 1], A3 = ah[4 + 2 * kk + 1];
            u32 L0 = al[2 * kk], L1 = al[4 + 2 * kk];
            u32 L2 = al[2 * kk + 1], L3 = al[4 + 2 * kk + 1];
            mma_tf32(d0, d1, d2, d3, A0, A1, A2, A3, bHi[kk][nh][0], bHi[kk][nh][1]);
            mma_tf32(d0, d1, d2, d3, A0, A1, A2, A3, bLo[kk][nh][0], bLo[kk][nh][1]);
            mma_tf32(d0, d1, d2, d3, L0, L1, L2, L3, bHi[kk][nh][0], bHi[kk][nh][1]);
        }
        // D-frag: (grp, 8nh+2tid..+1) and (grp+8, same cols) -> two STG.64.
        int e0 = sbase + 8 * nh;
        int e1 = e0 + 128;
        if (!GUARD || e0 < total) __stcs((float2*)&gout[e0], make_float2(d0, d1));
        if (!GUARD || e1 < total) __stcs((float2*)&gout[e1], make_float2(d2, d3));
    }
}

template <bool GUARD>
__global__ __launch_bounds__(256, 2)
void xattn_kernel(const float* __restrict__ gin, float* __restrict__ gout,
                  const float* __restrict__ w_in, const float* __restrict__ b_in,
                  const float* __restrict__ w_out, const float* __restrict__ b_out,
                  int total, int ntiles) {
    __shared__ float sM[DIMN * DIMN];   // sM[j*16+i] = M[j][i] = (Wout @ Wv)[j][i]
    __shared__ float sC[DIMN];          // c = Wout @ bv + bout

    int t = threadIdx.x;
    {   // per-CTA weight folding
        int j = t >> 4, i = t & 15;
        float m = 0.f;
#pragma unroll
        for (int k = 0; k < DIMN; k++)
            m += w_out[j * DIMN + k] * w_in[(2 * DIMN + k) * DIMN + i];  // Wv rows 32..47
        sM[j * DIMN + i] = m;
        if (i == 0) {
            float c = b_out[j];
#pragma unroll
            for (int k = 0; k < DIMN; k++)
                c += w_out[j * DIMN + k] * b_in[2 * DIMN + k];
            sC[j] = c;
        }
    }
    __syncthreads();

    const int lane = t & 31, grp = lane >> 2, tid = lane & 3;

    // B-fragments: B[k][n] = M^T[k][n] -> b_h = M[8nh+grp][8kk+tid+4h], split hi/lo.
    u32 bHi[2][2][2], bLo[2][2][2];
#pragma unroll
    for (int kk = 0; kk < 2; kk++)
#pragma unroll
        for (int nh = 0; nh < 2; nh++)
#pragma unroll
            for (int h = 0; h < 2; h++) {
                float m = sM[(8 * nh + grp) * DIMN + 8 * kk + tid + 4 * h];
                u32 u = __float_as_uint(m) & 0xffffe000u;
                bHi[kk][nh][h] = u;
                bLo[kk][nh][h] = __float_as_uint(m - __uint_as_float(u));
            }
    float cb[2][2];
#pragma unroll
    for (int nh = 0; nh < 2; nh++) {
        cb[nh][0] = sC[8 * nh + 2 * tid];
        cb[nh][1] = sC[8 * nh + 2 * tid + 1];
    }

    const int W = gridDim.x << 3;              // total warps (persistent)
    int T = (blockIdx.x << 3) + (t >> 5);
    if (T >= ntiles) return;
    const int lofs = grp * 16 + tid;

    float v0[8], v1[8], v2[8];
    load_tile<GUARD>(v0, gin, T * 256 + lofs, true, total);
    load_tile<GUARD>(v1, gin, (T + W) * 256 + lofs, T + W < ntiles, total);

    while (true) {
        load_tile<GUARD>(v2, gin, (T + 2 * W) * 256 + lofs, T + 2 * W < ntiles, total);
        proc_tile<GUARD>(v0, gout, T, grp, tid, total, bHi, bLo, cb);
        T += W; if (T >= ntiles) return;

        load_tile<GUARD>(v0, gin, (T + 2 * W) * 256 + lofs, T + 2 * W < ntiles, total);
        proc_tile<GUARD>(v1, gout, T, grp, tid, total, bHi, bLo, cb);
        T += W; if (T >= ntiles) return;

        load_tile<GUARD>(v1, gin, (T + 2 * W) * 256 + lofs, T + 2 * W < ntiles, total);
        proc_tile<GUARD>(v2, gout, T, grp, tid, total, bHi, bLo, cb);
        T += W; if (T >= ntiles) return;
    }
}

extern "C" void kernel_launch(void* const* d_in, const int* in_sizes, int n_in,
                              void* d_out, int out_size) {
    // inputs: 0 fp_16 (unused), 1 chem_16, 2 in_proj_weight, 3 in_proj_bias,
    //         4 out_proj_weight, 5 out_proj_bias
    const float* chem  = (const float*)d_in[1];
    const float* w_in  = (const float*)d_in[2];
    const float* b_in  = (const float*)d_in[3];
    const float* w_out = (const float*)d_in[4];
    const float* b_out = (const float*)d_in[5];

    int total  = in_sizes[1];                  // floats (rows * 16)
    int ntiles = (total + 255) / 256;
    int blocks = (ntiles + 7) / 8;
    if (blocks > NCTA) blocks = NCTA;

    if (total % 256 == 0) {
        xattn_kernel<false><<<blocks, 256>>>((const float*)chem, (float*)d_out,
                                             w_in, b_in, w_out, b_out,
                                             total, ntiles);
    } else {
        xattn_kernel<true><<<blocks, 256>>>((const float*)chem, (float*)d_out,
                                            w_in, b_in, w_out, b_out,
                                            total, ntiles);
    }
}

// round 14
// speedup vs baseline: 1.4709x; 1.0863x over previous
#include <cuda_runtime.h>
#include <cstdint>

// out = chem @ (Wout @ Wv)^T + (Wout @ bv + bout)   (softmax over singleton == 1)
//
// Tensor-core path (R13): folded 16x16 matvec as mma.sync.m16n8k8.tf32,
// 3-term compensated (x_hi*M_hi + x_hi*M_lo + x_lo*M_hi) -> fp32-grade
// accuracy. A-fragments loaded DIRECTLY from gmem (8 LDG.32/warp-tile,
// sectors fully covered across the cc pairs via L1), D-fragments stored
// directly (4 STG.64, full sectors). Persistent grid, per-warp 3-buffer
// pipeline. NEW vs R13: 3 CTAs/SM (regs=76 fits) -> 24 warps/SM,
// 48 KB/SM in flight, grid 444.

#define DIMN 16
#define NCTA 444          // 3 per SM x 148

typedef unsigned int u32;

__device__ __forceinline__ void mma_tf32(float& d0, float& d1, float& d2, float& d3,
                                         u32 a0, u32 a1, u32 a2, u32 a3,
                                         u32 b0, u32 b1) {
    asm("mma.sync.aligned.m16n8k8.row.col.f32.tf32.tf32.f32 "
        "{%0,%1,%2,%3}, {%4,%5,%6,%7}, {%8,%9}, {%0,%1,%2,%3};"
        : "+f"(d0), "+f"(d1), "+f"(d2), "+f"(d3)
        : "r"(a0), "r"(a1), "r"(a2), "r"(a3), "r"(b0), "r"(b1));
}

// Tile = 16 consecutive rows = 256 floats = 1 KB, processed by one warp.
// Lane (grp = lane>>2, tid = lane&3) loads x[grp + 8rr][tid + 4cc], rr<2, cc<4.
template <bool GUARD>
__device__ __forceinline__ void load_tile(float v[8], const float* __restrict__ gin,
                                          int lbase, bool live, int total) {
    if (!live) return;
#pragma unroll
    for (int j = 0; j < 8; j++) {
        int e = lbase + (j >> 2) * 128 + (j & 3) * 4;
        if (GUARD) v[j] = (e < total) ? gin[e] : 0.f;
        else       v[j] = gin[e];
    }
}

template <bool GUARD>
__device__ __forceinline__ void proc_tile(const float v[8], float* __restrict__ gout,
                                          int T, int grp, int tid, int total,
                                          const u32 bHi[2][2][2],
                                          const u32 bLo[2][2][2],
                                          const float cb[2][2]) {
    // Split x into tf32-exact hi + residual lo.
    u32 ah[8], al[8];
#pragma unroll
    for (int j = 0; j < 8; j++) {
        u32 u = __float_as_uint(v[j]) & 0xffffe000u;
        ah[j] = u;
        al[j] = __float_as_uint(v[j] - __uint_as_float(u));
    }
    int sbase = T * 256 + grp * 16 + 2 * tid;
#pragma unroll
    for (int nh = 0; nh < 2; nh++) {
        float d0 = cb[nh][0], d1 = cb[nh][1], d2 = d0, d3 = d1;  // bias seed
#pragma unroll
        for (int kk = 0; kk < 2; kk++) {
            u32 A0 = ah[2 * kk], A1 = ah[4 + 2 * kk];
            u32 A2 = ah[2 * kk + 1], A3 = ah[4 + 2 * kk + 1];
            u32 L0 = al[2 * kk], L1 = al[4 + 2 * kk];
            u32 L2 = al[2 * kk + 1], L3 = al[4 + 2 * kk + 1];
            mma_tf32(d0, d1, d2, d3, A0, A1, A2, A3, bHi[kk][nh][0], bHi[kk][nh][1]);
            mma_tf32(d0, d1, d2, d3, A0, A1, A2, A3, bLo[kk][nh][0], bLo[kk][nh][1]);
            mma_tf32(d0, d1, d2, d3, L0, L1, L2, L3, bHi[kk][nh][0], bHi[kk][nh][1]);
        }
        // D-frag: (grp, 8nh+2tid..+1) and (grp+8, same cols) -> two STG.64.
        int e0 = sbase + 8 * nh;
        int e1 = e0 + 128;
        if (!GUARD || e0 < total) __stcs((float2*)&gout[e0], make_float2(d0, d1));
        if (!GUARD || e1 < total) __stcs((float2*)&gout[e1], make_float2(d2, d3));
    }
}

template <bool GUARD>
__global__ __launch_bounds__(256, 3)
void xattn_kernel(const float* __restrict__ gin, float* __restrict__ gout,
                  const float* __restrict__ w_in, const float* __restrict__ b_in,
                  const float* __restrict__ w_out, const float* __restrict__ b_out,
                  int total, int ntiles) {
    __shared__ float sM[DIMN * DIMN];   // sM[j*16+i] = (Wout @ Wv)[j][i]
    __shared__ float sC[DIMN];          // c = Wout @ bv + bout

    int t = threadIdx.x;
    {   // per-CTA weight folding
        int j = t >> 4, i = t & 15;
        float m = 0.f;
#pragma unroll
        for (int k = 0; k < DIMN; k++)
            m += w_out[j * DIMN + k] * w_in[(2 * DIMN + k) * DIMN + i];  // Wv rows 32..47
        sM[j * DIMN + i] = m;
        if (i == 0) {
            float c = b_out[j];
#pragma unroll
            for (int k = 0; k < DIMN; k++)
                c += w_out[j * DIMN + k] * b_in[2 * DIMN + k];
            sC[j] = c;
        }
    }
    __syncthreads();

    const int lane = t & 31, grp = lane >> 2, tid = lane & 3;

    // B-fragments: b_h = M[8nh+grp][8kk+tid+4h], split hi/lo.
    u32 bHi[2][2][2], bLo[2][2][2];
#pragma unroll
    for (int kk = 0; kk < 2; kk++)
#pragma unroll
        for (int nh = 0; nh < 2; nh++)
#pragma unroll
            for (int h = 0; h < 2; h++) {
                float m = sM[(8 * nh + grp) * DIMN + 8 * kk + tid + 4 * h];
                u32 u = __float_as_uint(m) & 0xffffe000u;
                bHi[kk][nh][h] = u;
                bLo[kk][nh][h] = __float_as_uint(m - __uint_as_float(u));
            }
    float cb[2][2];
#pragma unroll
    for (int nh = 0; nh < 2; nh++) {
        cb[nh][0] = sC[8 * nh + 2 * tid];
        cb[nh][1] = sC[8 * nh + 2 * tid + 1];
    }

    const int W = gridDim.x << 3;              // total warps (persistent)
    int T = (blockIdx.x << 3) + (t >> 5);
    if (T >= ntiles) return;
    const int lofs = grp * 16 + tid;

    float v0[8], v1[8], v2[8];
    load_tile<GUARD>(v0, gin, T * 256 + lofs, true, total);
    load_tile<GUARD>(v1, gin, (T + W) * 256 + lofs, T + W < ntiles, total);

    while (true) {
        load_tile<GUARD>(v2, gin, (T + 2 * W) * 256 + lofs, T + 2 * W < ntiles, total);
        proc_tile<GUARD>(v0, gout, T, grp, tid, total, bHi, bLo, cb);
        T += W; if (T >= ntiles) return;

        load_tile<GUARD>(v0, gin, (T + 2 * W) * 256 + lofs, T + 2 * W < ntiles, total);
        proc_tile<GUARD>(v1, gout, T, grp, tid, total, bHi, bLo, cb);
        T += W; if (T >= ntiles) return;

        load_tile<GUARD>(v1, gin, (T + 2 * W) * 256 + lofs, T + 2 * W < ntiles, total);
        proc_tile<GUARD>(v2, gout, T, grp, tid, total, bHi, bLo, cb);
        T += W; if (T >= ntiles) return;
    }
}

extern "C" void kernel_launch(void* const* d_in, const int* in_sizes, int n_in,
                              void* d_out, int out_size) {
    // inputs: 0 fp_16 (unused), 1 chem_16, 2 in_proj_weight, 3 in_proj_bias,
    //         4 out_proj_weight, 5 out_proj_bias
    const float* chem  = (const float*)d_in[1];
    const float* w_in  = (const float*)d_in[2];
    const float* b_in  = (const float*)d_in[3];
    const float* w_out = (const float*)d_in[4];
    const float* b_out = (const float*)d_in[5];

    int total  = in_sizes[1];                  // floats (rows * 16)
    int ntiles = (total + 255) / 256;
    int blocks = (ntiles + 7) / 8;
    if (blocks > NCTA) blocks = NCTA;

    if (total % 256 == 0) {
        xattn_kernel<false><<<blocks, 256>>>((const float*)chem, (float*)d_out,
                                             w_in, b_in, w_out, b_out,
                                             total, ntiles);
    } else {
        xattn_kernel<true><<<blocks, 256>>>((const float*)chem, (float*)d_out,
                                            w_in, b_in, w_out, b_out,
                                            total, ntiles);
    }
}